// round 2
// baseline (speedup 1.0000x reference)
#include <cuda_runtime.h>
#include <cstdint>

#define BATCH 256
#define NNODE 2048
#define EMB   128
#define HEADS 8
#define DK    16
#define SPLITS 4
#define CHUNK (NNODE / SPLITS)   // 512 rows per CTA, 64 per warp

// ---- scratch (no allocations allowed in kernel_launch) ----
__device__ float g_P[BATCH * HEADS * EMB];        // 1 MB : P[b,h,:] = scale * Wk^T q  (per-head slice)
__device__ float g_qb[BATCH * HEADS];             // scale * q_h . bk_h
__device__ float g_partA[SPLITS * BATCH * HEADS * EMB]; // 4 MB partial weighted-emb sums
__device__ float g_partL[SPLITS * BATCH * HEADS];       // partial softmax denominators
__device__ int   g_mask_fmt;                      // 1 = 4-byte elements (i32/f32), 0 = 1-byte

// ============================================================================
// Kernel 1: q = ctx@Wq^T+bq ; P = scale*Wk^T q (per head) ; qb = scale*q.bk
// Also probes the mask buffer's element width (deterministic, input-only).
// ============================================================================
__global__ void k_prep(const float* __restrict__ ctx,
                       const float* __restrict__ Wq, const float* __restrict__ bq,
                       const float* __restrict__ Wk, const float* __restrict__ bk,
                       const unsigned* __restrict__ maskw)
{
    const int b = blockIdx.x, t = threadIdx.x;   // 128 threads
    __shared__ float cs[EMB], qs[EMB];
    cs[t] = ctx[b * EMB + t];
    __syncthreads();

    float acc = bq[t];
#pragma unroll 8
    for (int d = 0; d < EMB; d++) acc = fmaf(cs[d], Wq[t * EMB + d], acc);
    qs[t] = acc;
    __syncthreads();

    const float scale = 0.25f;   // 1/sqrt(16)
#pragma unroll
    for (int h = 0; h < HEADS; h++) {
        float p = 0.f;
#pragma unroll
        for (int d = 0; d < DK; d++)
            p = fmaf(qs[h * DK + d], Wk[(h * DK + d) * EMB + t], p);
        g_P[(b * HEADS + h) * EMB + t] = p * scale;
    }
    if (t < HEADS) {
        float s = 0.f;
#pragma unroll
        for (int d = 0; d < DK; d++) s = fmaf(qs[t * DK + d], bk[t * DK + d], s);
        g_qb[b * HEADS + t] = s * scale;
    }

    // Mask element-width probe: 4-byte bools are words in {0, 1, 0x3F800000}.
    // Byte-packed bools make such words only ~12.5% of the time.
    if (b == 0 && t == 0) {
        int good = 0;
        for (int i = 0; i < 1024; i++) {
            unsigned w = maskw[i];
            good += (w == 0u) || (w == 1u) || (w == 0x3F800000u);
        }
        g_mask_fmt = (good >= 922) ? 1 : 0;
    }
}

// ============================================================================
// Kernel 2: streaming masked softmax + weighted embedding accumulation.
// Grid (SPLITS, BATCH), 256 threads. Each warp owns 64 contiguous rows,
// skips masked rows exactly (exp(-1e6)==0 in f32), no max-subtraction needed
// (logit magnitudes are O(1)). acc[h][4] per lane; 9-shfl multi-head reduce.
// ============================================================================
__global__ void __launch_bounds__(256) k_attn(const float* __restrict__ emb,
                                              const void* __restrict__ maskp)
{
    const int sIdx = blockIdx.x, b = blockIdx.y;
    const int w = threadIdx.x >> 5, lane = threadIdx.x & 31;
    const int myHead = (lane >> 2) & 7;

    // Per-lane slice of P: p[h][j] covers dims lane*4 .. lane*4+3
    float p[8][4];
    const float4* Pv = (const float4*)g_P + (size_t)b * (HEADS * EMB / 4);
#pragma unroll
    for (int h = 0; h < 8; h++) {
        float4 t4 = Pv[h * 32 + lane];
        p[h][0] = t4.x; p[h][1] = t4.y; p[h][2] = t4.z; p[h][3] = t4.w;
    }
    const float qb_l = g_qb[b * HEADS + myHead];

    const int rowBase = sIdx * CHUNK + w * 64;
    const size_t mbase = (size_t)b * NNODE + rowBase;

    bool um0, um1;   // "unmasked" = keep
    if (g_mask_fmt) {
        const unsigned* mi = (const unsigned*)maskp;
        um0 = (mi[mbase + lane]      == 0u);
        um1 = (mi[mbase + 32 + lane] == 0u);
    } else {
        const unsigned char* mu = (const unsigned char*)maskp;
        um0 = (mu[mbase + lane]      == 0);
        um1 = (mu[mbase + 32 + lane] == 0);
    }
    unsigned long long rem =
        (unsigned long long)__ballot_sync(0xffffffffu, um0) |
        ((unsigned long long)__ballot_sync(0xffffffffu, um1) << 32);

    float acc[8][4];
#pragma unroll
    for (int h = 0; h < 8; h++) { acc[h][0]=0.f; acc[h][1]=0.f; acc[h][2]=0.f; acc[h][3]=0.f; }
    float lacc = 0.f;

    const float4* e4 = (const float4*)emb + ((size_t)b * NNODE + rowBase) * (EMB / 4) + lane;

    // Software-pipelined walk over unmasked rows (prefetch next row's float4).
    int i_cur = rem ? (__ffsll((long long)rem) - 1) : 64;
    float4 eN = make_float4(0.f, 0.f, 0.f, 0.f);
    if (i_cur < 64) eN = e4[(size_t)i_cur * (EMB / 4)];

    while (i_cur < 64) {
        rem &= rem - 1;
        int i_nx = rem ? (__ffsll((long long)rem) - 1) : 64;
        float4 e = eN;
        if (i_nx < 64) eN = e4[(size_t)i_nx * (EMB / 4)];

        // scores: 8 per-lane partial dots over this lane's 4 dims
        float v[8];
#pragma unroll
        for (int h = 0; h < 8; h++)
            v[h] = fmaf(p[h][3], e.w, fmaf(p[h][2], e.z, fmaf(p[h][1], e.y, p[h][0] * e.x)));

        // 9-shfl half-exchange butterfly: lane ends with full dot for head (lane>>2)&7
#pragma unroll
        for (int j = 0; j < 4; j++) {
            float o = __shfl_xor_sync(0xffffffffu, (lane & 16) ? v[j] : v[j + 4], 16);
            v[j] = ((lane & 16) ? v[j + 4] : v[j]) + o;
        }
#pragma unroll
        for (int j = 0; j < 2; j++) {
            float o = __shfl_xor_sync(0xffffffffu, (lane & 8) ? v[j] : v[j + 2], 8);
            v[j] = ((lane & 8) ? v[j + 2] : v[j]) + o;
        }
        {
            float o = __shfl_xor_sync(0xffffffffu, (lane & 4) ? v[0] : v[1], 4);
            v[0] = ((lane & 4) ? v[1] : v[0]) + o;
        }
        v[0] += __shfl_xor_sync(0xffffffffu, v[0], 2);
        v[0] += __shfl_xor_sync(0xffffffffu, v[0], 1);

        float wexp = __expf(v[0] + qb_l);
        lacc += wexp;

#pragma unroll
        for (int h = 0; h < 8; h++) {
            float wh = __shfl_sync(0xffffffffu, wexp, h * 4);
            acc[h][0] = fmaf(wh, e.x, acc[h][0]);
            acc[h][1] = fmaf(wh, e.y, acc[h][1]);
            acc[h][2] = fmaf(wh, e.z, acc[h][2]);
            acc[h][3] = fmaf(wh, e.w, acc[h][3]);
        }
        i_cur = i_nx;
    }

    // Cross-warp reduce in SMEM, one partial write per CTA.
    __shared__ float4 sAcc[8 * 8 * 32];   // [warp][head][lane], 32 KB
    __shared__ float  sL[8][8];
#pragma unroll
    for (int h = 0; h < 8; h++)
        sAcc[(w * 8 + h) * 32 + lane] = make_float4(acc[h][0], acc[h][1], acc[h][2], acc[h][3]);
    if ((lane & 3) == 0) sL[w][myHead] = lacc;
    __syncthreads();

    const int t = threadIdx.x;
    float4 a = sAcc[t];
#pragma unroll
    for (int ww = 1; ww < 8; ww++) {
        float4 o = sAcc[ww * 256 + t];
        a.x += o.x; a.y += o.y; a.z += o.z; a.w += o.w;
    }
    ((float4*)g_partA)[((size_t)sIdx * BATCH + b) * 256 + t] = a;
    if (t < 8) {
        float l = 0.f;
#pragma unroll
        for (int ww = 0; ww < 8; ww++) l += sL[ww][t];
        g_partL[(sIdx * BATCH + b) * HEADS + t] = l;
    }
}

// ============================================================================
// Kernel 3: combine splits, normalize, apply V projection to the tiny
// per-head context vectors: out[b,o] = (ctx_h/l_h) . Wv[o,:] + bv[o].
// ============================================================================
__global__ void k_combine(const float* __restrict__ Wv, const float* __restrict__ bv,
                          float* __restrict__ out)
{
    const int b = blockIdx.x, t = threadIdx.x;   // 128 threads
    __shared__ float ctxs[HEADS][EMB];
    __shared__ float ls[HEADS];
    if (t < HEADS) {
        float l = 0.f;
        for (int s = 0; s < SPLITS; s++) l += g_partL[(s * BATCH + b) * HEADS + t];
        ls[t] = l;
    }
    __syncthreads();
#pragma unroll
    for (int h = 0; h < HEADS; h++) {
        float a = 0.f;
        for (int s = 0; s < SPLITS; s++)
            a += g_partA[(((size_t)s * BATCH + b) * HEADS + h) * EMB + t];
        ctxs[h][t] = a / ls[h];
    }
    __syncthreads();
    const int h = t >> 4;
    float r = bv[t];
#pragma unroll 8
    for (int d = 0; d < EMB; d++) r = fmaf(ctxs[h][d], Wv[t * EMB + d], r);
    out[b * EMB + t] = r;
}

// ============================================================================
extern "C" void kernel_launch(void* const* d_in, const int* in_sizes, int n_in,
                              void* d_out, int out_size)
{
    const float* ctx = (const float*)d_in[0];
    const float* emb = (const float*)d_in[1];
    const void*  msk = d_in[2];
    const float* Wq  = (const float*)d_in[3];
    const float* bq  = (const float*)d_in[4];
    const float* Wk  = (const float*)d_in[5];
    const float* bk  = (const float*)d_in[6];
    const float* Wv  = (const float*)d_in[7];
    const float* bv  = (const float*)d_in[8];
    float* out = (float*)d_out;

    k_prep<<<BATCH, 128>>>(ctx, Wq, bq, Wk, bk, (const unsigned*)msk);
    k_attn<<<dim3(SPLITS, BATCH), 256>>>(emb, msk);
    k_combine<<<BATCH, 128>>>(Wv, bv, out);
}

// round 6
// speedup vs baseline: 1.0079x; 1.0079x over previous
#include <cuda_runtime.h>
#include <cstdint>

#define BATCH 256
#define NNODE 2048
#define EMB   128
#define HEADS 8
#define DK    16
#define SPLITS 4
#define CHUNK (NNODE / SPLITS)   // 512 rows per CTA, 64 per warp

// ---- scratch (no allocations allowed in kernel_launch) ----
__device__ float g_P[BATCH * HEADS * EMB];        // 1 MB : P[b,h,:] = scale * Wk^T q  (per-head slice)
__device__ float g_qb[BATCH * HEADS];             // scale * q_h . bk_h
__device__ float g_partA[SPLITS * BATCH * HEADS * EMB]; // 4 MB partial weighted-emb sums
__device__ float g_partL[SPLITS * BATCH * HEADS];       // partial softmax denominators
__device__ int   g_mask_fmt;                      // 1 = 4-byte elements (i32/f32), 0 = 1-byte

// ============================================================================
// Kernel 1: q = ctx@Wq^T+bq ; P = scale*Wk^T q (per head) ; qb = scale*q.bk
// Also probes the mask buffer's element width (deterministic, input-only).
// ============================================================================
__global__ void k_prep(const float* __restrict__ ctx,
                       const float* __restrict__ Wq, const float* __restrict__ bq,
                       const float* __restrict__ Wk, const float* __restrict__ bk,
                       const unsigned* __restrict__ maskw)
{
    const int b = blockIdx.x, t = threadIdx.x;   // 128 threads
    __shared__ float cs[EMB], qs[EMB];
    cs[t] = ctx[b * EMB + t];
    __syncthreads();

    float acc = bq[t];
#pragma unroll 8
    for (int d = 0; d < EMB; d++) acc = fmaf(cs[d], Wq[t * EMB + d], acc);
    qs[t] = acc;
    __syncthreads();

    const float scale = 0.25f;   // 1/sqrt(16)
#pragma unroll
    for (int h = 0; h < HEADS; h++) {
        float p = 0.f;
#pragma unroll
        for (int d = 0; d < DK; d++)
            p = fmaf(qs[h * DK + d], Wk[(h * DK + d) * EMB + t], p);
        g_P[(b * HEADS + h) * EMB + t] = p * scale;
    }
    if (t < HEADS) {
        float s = 0.f;
#pragma unroll
        for (int d = 0; d < DK; d++) s = fmaf(qs[t * DK + d], bk[t * DK + d], s);
        g_qb[b * HEADS + t] = s * scale;
    }

    // Mask element-width probe: 4-byte bools are words in {0, 1, 0x3F800000}.
    // Byte-packed bools make such words only ~12.5% of the time.
    if (b == 0 && t == 0) {
        int good = 0;
        for (int i = 0; i < 1024; i++) {
            unsigned w = maskw[i];
            good += (w == 0u) || (w == 1u) || (w == 0x3F800000u);
        }
        g_mask_fmt = (good >= 922) ? 1 : 0;
    }
}

// ============================================================================
// Kernel 2: streaming masked softmax + weighted embedding accumulation.
// Grid (SPLITS, BATCH), 256 threads. Each warp owns 64 contiguous rows,
// skips masked rows exactly (exp(-1e6)==0 in f32), no max-subtraction needed
// (logit magnitudes are O(1)). acc[h][4] per lane; 9-shfl multi-head reduce.
// ============================================================================
__global__ void __launch_bounds__(256) k_attn(const float* __restrict__ emb,
                                              const void* __restrict__ maskp)
{
    const int sIdx = blockIdx.x, b = blockIdx.y;
    const int w = threadIdx.x >> 5, lane = threadIdx.x & 31;
    const int myHead = (lane >> 2) & 7;

    // Per-lane slice of P: p[h][j] covers dims lane*4 .. lane*4+3
    float p[8][4];
    const float4* Pv = (const float4*)g_P + (size_t)b * (HEADS * EMB / 4);
#pragma unroll
    for (int h = 0; h < 8; h++) {
        float4 t4 = Pv[h * 32 + lane];
        p[h][0] = t4.x; p[h][1] = t4.y; p[h][2] = t4.z; p[h][3] = t4.w;
    }
    const float qb_l = g_qb[b * HEADS + myHead];

    const int rowBase = sIdx * CHUNK + w * 64;
    const size_t mbase = (size_t)b * NNODE + rowBase;

    bool um0, um1;   // "unmasked" = keep
    if (g_mask_fmt) {
        const unsigned* mi = (const unsigned*)maskp;
        um0 = (mi[mbase + lane]      == 0u);
        um1 = (mi[mbase + 32 + lane] == 0u);
    } else {
        const unsigned char* mu = (const unsigned char*)maskp;
        um0 = (mu[mbase + lane]      == 0);
        um1 = (mu[mbase + 32 + lane] == 0);
    }
    unsigned long long rem =
        (unsigned long long)__ballot_sync(0xffffffffu, um0) |
        ((unsigned long long)__ballot_sync(0xffffffffu, um1) << 32);

    float acc[8][4];
#pragma unroll
    for (int h = 0; h < 8; h++) { acc[h][0]=0.f; acc[h][1]=0.f; acc[h][2]=0.f; acc[h][3]=0.f; }
    float lacc = 0.f;

    const float4* e4 = (const float4*)emb + ((size_t)b * NNODE + rowBase) * (EMB / 4) + lane;

    // Software-pipelined walk over unmasked rows (prefetch next row's float4).
    int i_cur = rem ? (__ffsll((long long)rem) - 1) : 64;
    float4 eN = make_float4(0.f, 0.f, 0.f, 0.f);
    if (i_cur < 64) eN = e4[(size_t)i_cur * (EMB / 4)];

    while (i_cur < 64) {
        rem &= rem - 1;
        int i_nx = rem ? (__ffsll((long long)rem) - 1) : 64;
        float4 e = eN;
        if (i_nx < 64) eN = e4[(size_t)i_nx * (EMB / 4)];

        // scores: 8 per-lane partial dots over this lane's 4 dims
        float v[8];
#pragma unroll
        for (int h = 0; h < 8; h++)
            v[h] = fmaf(p[h][3], e.w, fmaf(p[h][2], e.z, fmaf(p[h][1], e.y, p[h][0] * e.x)));

        // 9-shfl half-exchange butterfly: lane ends with full dot for head (lane>>2)&7
#pragma unroll
        for (int j = 0; j < 4; j++) {
            float o = __shfl_xor_sync(0xffffffffu, (lane & 16) ? v[j] : v[j + 4], 16);
            v[j] = ((lane & 16) ? v[j + 4] : v[j]) + o;
        }
#pragma unroll
        for (int j = 0; j < 2; j++) {
            float o = __shfl_xor_sync(0xffffffffu, (lane & 8) ? v[j] : v[j + 2], 8);
            v[j] = ((lane & 8) ? v[j + 2] : v[j]) + o;
        }
        {
            float o = __shfl_xor_sync(0xffffffffu, (lane & 4) ? v[0] : v[1], 4);
            v[0] = ((lane & 4) ? v[1] : v[0]) + o;
        }
        v[0] += __shfl_xor_sync(0xffffffffu, v[0], 2);
        v[0] += __shfl_xor_sync(0xffffffffu, v[0], 1);

        float wexp = __expf(v[0] + qb_l);
        lacc += wexp;

#pragma unroll
        for (int h = 0; h < 8; h++) {
            float wh = __shfl_sync(0xffffffffu, wexp, h * 4);
            acc[h][0] = fmaf(wh, e.x, acc[h][0]);
            acc[h][1] = fmaf(wh, e.y, acc[h][1]);
            acc[h][2] = fmaf(wh, e.z, acc[h][2]);
            acc[h][3] = fmaf(wh, e.w, acc[h][3]);
        }
        i_cur = i_nx;
    }

    // Cross-warp reduce in SMEM, one partial write per CTA.
    __shared__ float4 sAcc[8 * 8 * 32];   // [warp][head][lane], 32 KB
    __shared__ float  sL[8][8];
#pragma unroll
    for (int h = 0; h < 8; h++)
        sAcc[(w * 8 + h) * 32 + lane] = make_float4(acc[h][0], acc[h][1], acc[h][2], acc[h][3]);
    if ((lane & 3) == 0) sL[w][myHead] = lacc;
    __syncthreads();

    const int t = threadIdx.x;
    float4 a = sAcc[t];
#pragma unroll
    for (int ww = 1; ww < 8; ww++) {
        float4 o = sAcc[ww * 256 + t];
        a.x += o.x; a.y += o.y; a.z += o.z; a.w += o.w;
    }
    ((float4*)g_partA)[((size_t)sIdx * BATCH + b) * 256 + t] = a;
    if (t < 8) {
        float l = 0.f;
#pragma unroll
        for (int ww = 0; ww < 8; ww++) l += sL[ww][t];
        g_partL[(sIdx * BATCH + b) * HEADS + t] = l;
    }
}

// ============================================================================
// Kernel 3: combine splits, normalize, apply V projection to the tiny
// per-head context vectors: out[b,o] = (ctx_h/l_h) . Wv[o,:] + bv[o].
// ============================================================================
__global__ void k_combine(const float* __restrict__ Wv, const float* __restrict__ bv,
                          float* __restrict__ out)
{
    const int b = blockIdx.x, t = threadIdx.x;   // 128 threads
    __shared__ float ctxs[HEADS][EMB];
    __shared__ float ls[HEADS];
    if (t < HEADS) {
        float l = 0.f;
        for (int s = 0; s < SPLITS; s++) l += g_partL[(s * BATCH + b) * HEADS + t];
        ls[t] = l;
    }
    __syncthreads();
#pragma unroll
    for (int h = 0; h < HEADS; h++) {
        float a = 0.f;
        for (int s = 0; s < SPLITS; s++)
            a += g_partA[(((size_t)s * BATCH + b) * HEADS + h) * EMB + t];
        ctxs[h][t] = a / ls[h];
    }
    __syncthreads();
    const int h = t >> 4;
    float r = bv[t];
#pragma unroll 8
    for (int d = 0; d < EMB; d++) r = fmaf(ctxs[h][d], Wv[t * EMB + d], r);
    out[b * EMB + t] = r;
}

// ============================================================================
extern "C" void kernel_launch(void* const* d_in, const int* in_sizes, int n_in,
                              void* d_out, int out_size)
{
    const float* ctx = (const float*)d_in[0];
    const float* emb = (const float*)d_in[1];
    const void*  msk = d_in[2];
    const float* Wq  = (const float*)d_in[3];
    const float* bq  = (const float*)d_in[4];
    const float* Wk  = (const float*)d_in[5];
    const float* bk  = (const float*)d_in[6];
    const float* Wv  = (const float*)d_in[7];
    const float* bv  = (const float*)d_in[8];
    float* out = (float*)d_out;

    k_prep<<<BATCH, 128>>>(ctx, Wq, bq, Wk, bk, (const unsigned*)msk);
    k_attn<<<dim3(SPLITS, BATCH), 256>>>(emb, msk);
    k_combine<<<BATCH, 128>>>(Wv, bv, out);
}

// round 9
// speedup vs baseline: 1.5494x; 1.5373x over previous
#include <cuda_runtime.h>
#include <cstdint>

#define BATCH 256
#define NNODE 2048
#define EMB   128
#define HEADS 8
#define DK    16
#define SPLITS 8
#define CHUNK (NNODE / SPLITS)   // 256 rows per CTA, 64 per warp (4 warps)

// ---- scratch (no allocations allowed in kernel_launch) ----
__device__ float g_P[BATCH * HEADS * EMB];                 // P[b,h,:] = scale * Wk^T q
__device__ float g_qb[BATCH * HEADS];                      // scale * q_h . bk_h
__device__ float g_partA[SPLITS * BATCH * HEADS * EMB];    // 8 MB partial weighted-emb sums
__device__ float g_partL[SPLITS * BATCH * HEADS];          // partial softmax denominators
__device__ int   g_mask_fmt;                               // 1 = 4-byte elements, 0 = 1-byte

// ============================================================================
// Kernel 1: q = ctx@Wq^T+bq ; P = scale*Wk^T q (per head) ; qb = scale*q.bk
// Mask-format probe parallelized across the 128 threads of block 0.
// ============================================================================
__global__ void k_prep(const float* __restrict__ ctx,
                       const float* __restrict__ Wq, const float* __restrict__ bq,
                       const float* __restrict__ Wk, const float* __restrict__ bk,
                       const unsigned* __restrict__ maskw)
{
    const int b = blockIdx.x, t = threadIdx.x;   // 128 threads
    __shared__ float cs[EMB], qs[EMB];
    __shared__ int sGood;

    // Parallel mask element-width probe (block 0 only): 4-byte bools are words
    // in {0, 1, 0x3F800000}; byte-packed bools match only ~12.5% of the time.
    if (b == 0) {
        if (t == 0) sGood = 0;
        cs[t] = ctx[b * EMB + t];
        __syncthreads();
        int good = 0;
#pragma unroll
        for (int i = 0; i < 8; i++) {
            unsigned w = maskw[t * 8 + i];
            good += (w == 0u) || (w == 1u) || (w == 0x3F800000u);
        }
        atomicAdd(&sGood, good);
        __syncthreads();
        if (t == 0) g_mask_fmt = (sGood >= 922) ? 1 : 0;
    } else {
        cs[t] = ctx[b * EMB + t];
        __syncthreads();
    }

    // q[t] = bq[t] + ctx_b . Wq[t,:]  — float4 loads, 4 independent chains
    {
        const float4* wq4 = (const float4*)(Wq + t * EMB);
        float a0 = 0.f, a1 = 0.f, a2 = 0.f, a3 = 0.f;
#pragma unroll
        for (int i = 0; i < 32; i += 4) {
            float4 w0 = wq4[i], w1 = wq4[i + 1], w2 = wq4[i + 2], w3 = wq4[i + 3];
            a0 = fmaf(cs[4*i+ 0], w0.x, a0); a0 = fmaf(cs[4*i+ 1], w0.y, a0);
            a0 = fmaf(cs[4*i+ 2], w0.z, a0); a0 = fmaf(cs[4*i+ 3], w0.w, a0);
            a1 = fmaf(cs[4*i+ 4], w1.x, a1); a1 = fmaf(cs[4*i+ 5], w1.y, a1);
            a1 = fmaf(cs[4*i+ 6], w1.z, a1); a1 = fmaf(cs[4*i+ 7], w1.w, a1);
            a2 = fmaf(cs[4*i+ 8], w2.x, a2); a2 = fmaf(cs[4*i+ 9], w2.y, a2);
            a2 = fmaf(cs[4*i+10], w2.z, a2); a2 = fmaf(cs[4*i+11], w2.w, a2);
            a3 = fmaf(cs[4*i+12], w3.x, a3); a3 = fmaf(cs[4*i+13], w3.y, a3);
            a3 = fmaf(cs[4*i+14], w3.z, a3); a3 = fmaf(cs[4*i+15], w3.w, a3);
        }
        qs[t] = bq[t] + ((a0 + a1) + (a2 + a3));
    }
    __syncthreads();

    const float scale = 0.25f;   // 1/sqrt(16)
#pragma unroll
    for (int h = 0; h < HEADS; h++) {
        float p = 0.f;
#pragma unroll
        for (int d = 0; d < DK; d++)
            p = fmaf(qs[h * DK + d], Wk[(h * DK + d) * EMB + t], p);
        g_P[(b * HEADS + h) * EMB + t] = p * scale;
    }
    if (t < HEADS) {
        float s = 0.f;
#pragma unroll
        for (int d = 0; d < DK; d++) s = fmaf(qs[t * DK + d], bk[t * DK + d], s);
        g_qb[b * HEADS + t] = s * scale;
    }
}

// ============================================================================
// Kernel 2: streaming masked softmax + weighted embedding accumulation.
// Grid (SPLITS, BATCH), 128 threads (4 warps). Each warp owns 64 contiguous
// rows, skips masked rows exactly (exp(-1e6)==0 in f32). Prefetch depth 2.
// ============================================================================
__global__ void __launch_bounds__(128) k_attn(const float* __restrict__ emb,
                                              const void* __restrict__ maskp)
{
    const int sIdx = blockIdx.x, b = blockIdx.y;
    const int w = threadIdx.x >> 5, lane = threadIdx.x & 31;
    const int myHead = (lane >> 2) & 7;

    // Per-lane slice of P: p[h][j] covers dims lane*4 .. lane*4+3
    float p[8][4];
    const float4* Pv = (const float4*)g_P + (size_t)b * (HEADS * EMB / 4);
#pragma unroll
    for (int h = 0; h < 8; h++) {
        float4 t4 = Pv[h * 32 + lane];
        p[h][0] = t4.x; p[h][1] = t4.y; p[h][2] = t4.z; p[h][3] = t4.w;
    }
    const float qb_l = g_qb[b * HEADS + myHead];

    const int rowBase = sIdx * CHUNK + w * 64;
    const size_t mbase = (size_t)b * NNODE + rowBase;

    bool um0, um1;   // "unmasked" = keep
    if (g_mask_fmt) {
        const unsigned* mi = (const unsigned*)maskp;
        um0 = (mi[mbase + lane]      == 0u);
        um1 = (mi[mbase + 32 + lane] == 0u);
    } else {
        const unsigned char* mu = (const unsigned char*)maskp;
        um0 = (mu[mbase + lane]      == 0);
        um1 = (mu[mbase + 32 + lane] == 0);
    }
    unsigned long long rem =
        (unsigned long long)__ballot_sync(0xffffffffu, um0) |
        ((unsigned long long)__ballot_sync(0xffffffffu, um1) << 32);

    float acc[8][4];
#pragma unroll
    for (int h = 0; h < 8; h++) { acc[h][0]=0.f; acc[h][1]=0.f; acc[h][2]=0.f; acc[h][3]=0.f; }
    float lacc = 0.f;

    const float4* e4 = (const float4*)emb + ((size_t)b * NNODE + rowBase) * (EMB / 4) + lane;

    // Depth-2 software pipeline over unmasked rows.
    int i0 = rem ? (__ffsll((long long)rem) - 1) : 64;
    if (i0 < 64) rem &= rem - 1;
    int i1 = rem ? (__ffsll((long long)rem) - 1) : 64;
    if (i1 < 64) rem &= rem - 1;

    float4 e0 = make_float4(0.f,0.f,0.f,0.f), e1 = e0;
    if (i0 < 64) e0 = e4[(size_t)i0 * (EMB / 4)];
    if (i1 < 64) e1 = e4[(size_t)i1 * (EMB / 4)];

    while (i0 < 64) {
        int i2 = rem ? (__ffsll((long long)rem) - 1) : 64;
        if (i2 < 64) rem &= rem - 1;

        float4 e = e0;
        e0 = e1;
        if (i2 < 64) e1 = e4[(size_t)i2 * (EMB / 4)];

        // scores: 8 per-lane partial dots over this lane's 4 dims
        float v[8];
#pragma unroll
        for (int h = 0; h < 8; h++)
            v[h] = fmaf(p[h][3], e.w, fmaf(p[h][2], e.z, fmaf(p[h][1], e.y, p[h][0] * e.x)));

        // 9-shfl half-exchange butterfly: quad (4h..4h+3) ends with head h's dot
#pragma unroll
        for (int j = 0; j < 4; j++) {
            float o = __shfl_xor_sync(0xffffffffu, (lane & 16) ? v[j] : v[j + 4], 16);
            v[j] = ((lane & 16) ? v[j + 4] : v[j]) + o;
        }
#pragma unroll
        for (int j = 0; j < 2; j++) {
            float o = __shfl_xor_sync(0xffffffffu, (lane & 8) ? v[j] : v[j + 2], 8);
            v[j] = ((lane & 8) ? v[j + 2] : v[j]) + o;
        }
        {
            float o = __shfl_xor_sync(0xffffffffu, (lane & 4) ? v[0] : v[1], 4);
            v[0] = ((lane & 4) ? v[1] : v[0]) + o;
        }
        v[0] += __shfl_xor_sync(0xffffffffu, v[0], 2);
        v[0] += __shfl_xor_sync(0xffffffffu, v[0], 1);

        float wexp = __expf(v[0] + qb_l);
        lacc += wexp;

#pragma unroll
        for (int h = 0; h < 8; h++) {
            float wh = __shfl_sync(0xffffffffu, wexp, h * 4);
            acc[h][0] = fmaf(wh, e.x, acc[h][0]);
            acc[h][1] = fmaf(wh, e.y, acc[h][1]);
            acc[h][2] = fmaf(wh, e.z, acc[h][2]);
            acc[h][3] = fmaf(wh, e.w, acc[h][3]);
        }
        i0 = i1; i1 = i2;
    }

    // Cross-warp reduce in SMEM, one partial write per CTA.
    __shared__ float4 sAcc[4 * 8 * 32];   // [warp][head][lane], 16 KB
    __shared__ float  sL[4][8];
#pragma unroll
    for (int h = 0; h < 8; h++)
        sAcc[(w * 8 + h) * 32 + lane] = make_float4(acc[h][0], acc[h][1], acc[h][2], acc[h][3]);
    if ((lane & 3) == 0) sL[w][myHead] = lacc;
    __syncthreads();

    const int t = threadIdx.x;
    float4* outA = (float4*)g_partA + ((size_t)sIdx * BATCH + b) * 256;
#pragma unroll
    for (int r = 0; r < 2; r++) {
        int idx = r * 128 + t;            // [head][lane] flat index, 0..255
        float4 a = sAcc[idx];
#pragma unroll
        for (int ww = 1; ww < 4; ww++) {
            float4 o = sAcc[ww * 256 + idx];
            a.x += o.x; a.y += o.y; a.z += o.z; a.w += o.w;
        }
        outA[idx] = a;
    }
    if (t < 8) {
        float l = 0.f;
#pragma unroll
        for (int ww = 0; ww < 4; ww++) l += sL[ww][t];
        g_partL[(sIdx * BATCH + b) * HEADS + t] = l;
    }
}

// ============================================================================
// Kernel 3: combine splits, normalize, apply V projection to the tiny
// per-head context vectors: out[b,o] = (ctx_h/l_h) . Wv[o,:] + bv[o].
// ============================================================================
__global__ void k_combine(const float* __restrict__ Wv, const float* __restrict__ bv,
                          float* __restrict__ out)
{
    const int b = blockIdx.x, t = threadIdx.x;   // 128 threads
    __shared__ float ctxs[HEADS][EMB];
    __shared__ float ls[HEADS];
    if (t < HEADS) {
        float l = 0.f;
#pragma unroll
        for (int s = 0; s < SPLITS; s++) l += g_partL[(s * BATCH + b) * HEADS + t];
        ls[t] = l;
    }
    __syncthreads();
#pragma unroll
    for (int h = 0; h < HEADS; h++) {
        float a = 0.f;
#pragma unroll
        for (int s = 0; s < SPLITS; s++)
            a += g_partA[(((size_t)s * BATCH + b) * HEADS + h) * EMB + t];
        ctxs[h][t] = a / ls[h];
    }
    __syncthreads();
    const int h = t >> 4;
    float r = bv[t];
#pragma unroll 8
    for (int d = 0; d < EMB; d++) r = fmaf(ctxs[h][d], Wv[t * EMB + d], r);
    out[b * EMB + t] = r;
}

// ============================================================================
extern "C" void kernel_launch(void* const* d_in, const int* in_sizes, int n_in,
                              void* d_out, int out_size)
{
    const float* ctx = (const float*)d_in[0];
    const float* emb = (const float*)d_in[1];
    const void*  msk = d_in[2];
    const float* Wq  = (const float*)d_in[3];
    const float* bq  = (const float*)d_in[4];
    const float* Wk  = (const float*)d_in[5];
    const float* bk  = (const float*)d_in[6];
    const float* Wv  = (const float*)d_in[7];
    const float* bv  = (const float*)d_in[8];
    float* out = (float*)d_out;

    k_prep<<<BATCH, 128>>>(ctx, Wq, bq, Wk, bk, (const unsigned*)msk);
    k_attn<<<dim3(SPLITS, BATCH), 128>>>(emb, msk);
    k_combine<<<BATCH, 128>>>(Wv, bv, out);
}

// round 10
// speedup vs baseline: 1.7892x; 1.1548x over previous
#include <cuda_runtime.h>
#include <cstdint>

#define BATCH 256
#define NNODE 2048
#define EMB   128
#define HEADS 8
#define DK    16
#define SPLITS 8
#define CHUNK (NNODE / SPLITS)   // 256 rows per CTA, 64 per warp (4 warps)

// packed dual-fp32 ops (sm_103a FFMA2 path — only reachable via PTX)
#define FMA2(d, a, b, c) asm("fma.rn.f32x2 %0, %1, %2, %3;" : "=l"(d) : "l"(a), "l"(b), "l"(c))
#define MUL2(d, a, b)    asm("mul.rn.f32x2 %0, %1, %2;"     : "=l"(d) : "l"(a), "l"(b))

// ---- scratch (no allocations allowed in kernel_launch) ----
__device__ float g_P[BATCH * HEADS * EMB];                 // P[b,h,:] = scale * Wk^T q
__device__ float g_qb[BATCH * HEADS];                      // scale * q_h . bk_h
__device__ float g_partA[SPLITS * BATCH * HEADS * EMB];    // 8 MB partial weighted-emb sums
__device__ float g_partL[SPLITS * BATCH * HEADS];          // partial softmax denominators
__device__ int   g_mask_fmt;                               // 1 = 4-byte elements, 0 = 1-byte

// ============================================================================
// Kernel 1: q = ctx@Wq^T+bq ; P = scale*Wk^T q (per head) ; qb = scale*q.bk
// q mat-vec is warp-cooperative: 8 lanes per output row -> coalesced Wq reads
// (4 sectors per warp-inst instead of 32).
// ============================================================================
__global__ void k_prep(const float* __restrict__ ctx,
                       const float* __restrict__ Wq, const float* __restrict__ bq,
                       const float* __restrict__ Wk, const float* __restrict__ bk,
                       const unsigned* __restrict__ maskw)
{
    const int b = blockIdx.x, t = threadIdx.x;   // 128 threads
    __shared__ float cs[EMB], qs[EMB];
    __shared__ int sGood;

    // Parallel mask element-width probe (block 0 only): 4-byte bools are words
    // in {0, 1, 0x3F800000}; byte-packed bools match only ~12.5% of the time.
    if (b == 0) {
        if (t == 0) sGood = 0;
        cs[t] = ctx[b * EMB + t];
        __syncthreads();
        int good = 0;
#pragma unroll
        for (int i = 0; i < 8; i++) {
            unsigned w = maskw[t * 8 + i];
            good += (w == 0u) || (w == 1u) || (w == 0x3F800000u);
        }
        atomicAdd(&sGood, good);
        __syncthreads();
        if (t == 0) g_mask_fmt = (sGood >= 922) ? 1 : 0;
    } else {
        cs[t] = ctx[b * EMB + t];
        __syncthreads();
    }

    // q[r] = bq[r] + ctx_b . Wq[r,:] — 8-lane groups per row, coalesced.
    {
        const int w = t >> 5, lane = t & 31, g = lane >> 3, k8 = lane & 7;
        const float4* cs4 = (const float4*)cs;
#pragma unroll 4
        for (int i = 0; i < 8; i++) {
            const int r = w * 32 + i * 4 + g;
            const float4* wr = (const float4*)(Wq + r * EMB);
            float part = 0.f;
#pragma unroll
            for (int j = 0; j < 4; j++) {
                float4 wv = wr[k8 + 8 * j];
                float4 c  = cs4[k8 + 8 * j];
                part = fmaf(wv.x, c.x, part); part = fmaf(wv.y, c.y, part);
                part = fmaf(wv.z, c.z, part); part = fmaf(wv.w, c.w, part);
            }
            part += __shfl_xor_sync(0xffffffffu, part, 4);
            part += __shfl_xor_sync(0xffffffffu, part, 2);
            part += __shfl_xor_sync(0xffffffffu, part, 1);
            if (k8 == 0) qs[r] = part + bq[r];
        }
    }
    __syncthreads();

    const float scale = 0.25f;   // 1/sqrt(16)
#pragma unroll
    for (int h = 0; h < HEADS; h++) {
        float p = 0.f;
#pragma unroll
        for (int d = 0; d < DK; d++)
            p = fmaf(qs[h * DK + d], Wk[(h * DK + d) * EMB + t], p);
        g_P[(b * HEADS + h) * EMB + t] = p * scale;
    }
    if (t < HEADS) {
        float s = 0.f;
#pragma unroll
        for (int d = 0; d < DK; d++) s = fmaf(qs[t * DK + d], bk[t * DK + d], s);
        g_qb[b * HEADS + t] = s * scale;
    }
}

// ============================================================================
// Kernel 2: streaming masked softmax + weighted embedding accumulation.
// Grid (SPLITS, BATCH), 128 threads (4 warps). Each warp owns 64 contiguous
// rows, skips masked rows exactly (exp(-1e6)==0 in f32). Prefetch depth 2.
// Packed f32x2 FMAs halve FMA-pipe slots per row (64 -> 32).
// ============================================================================
__global__ void __launch_bounds__(128) k_attn(const float* __restrict__ emb,
                                              const void* __restrict__ maskp)
{
    const int sIdx = blockIdx.x, b = blockIdx.y;
    const int w = threadIdx.x >> 5, lane = threadIdx.x & 31;
    const int myHead = (lane >> 2) & 7;

    // Per-lane slice of P, pre-packed as f32x2 pairs: dims lane*4 .. lane*4+3
    unsigned long long p01[8], p23[8];
    {
        const ulonglong2* Pv = (const ulonglong2*)g_P + (size_t)b * (HEADS * EMB / 4);
#pragma unroll
        for (int h = 0; h < 8; h++) {
            ulonglong2 t2 = Pv[h * 32 + lane];
            p01[h] = t2.x; p23[h] = t2.y;
        }
    }
    const float qb_l = g_qb[b * HEADS + myHead];

    const int rowBase = sIdx * CHUNK + w * 64;
    const size_t mbase = (size_t)b * NNODE + rowBase;

    bool um0, um1;   // "unmasked" = keep
    if (g_mask_fmt) {
        const unsigned* mi = (const unsigned*)maskp;
        um0 = (mi[mbase + lane]      == 0u);
        um1 = (mi[mbase + 32 + lane] == 0u);
    } else {
        const unsigned char* mu = (const unsigned char*)maskp;
        um0 = (mu[mbase + lane]      == 0);
        um1 = (mu[mbase + 32 + lane] == 0);
    }
    unsigned long long rem =
        (unsigned long long)__ballot_sync(0xffffffffu, um0) |
        ((unsigned long long)__ballot_sync(0xffffffffu, um1) << 32);

    // Packed accumulators: acc01[h] = dims (4l, 4l+1), acc23[h] = (4l+2, 4l+3)
    unsigned long long acc01[8], acc23[8];
#pragma unroll
    for (int h = 0; h < 8; h++) { acc01[h] = 0ull; acc23[h] = 0ull; }
    float lacc = 0.f;

    const ulonglong2* e4 = (const ulonglong2*)emb + ((size_t)b * NNODE + rowBase) * (EMB / 4) + lane;

    // Depth-2 software pipeline over unmasked rows.
    int i0 = rem ? (__ffsll((long long)rem) - 1) : 64;
    if (i0 < 64) rem &= rem - 1;
    int i1 = rem ? (__ffsll((long long)rem) - 1) : 64;
    if (i1 < 64) rem &= rem - 1;

    ulonglong2 e0; e0.x = 0ull; e0.y = 0ull;
    ulonglong2 e1 = e0;
    if (i0 < 64) e0 = e4[(size_t)i0 * (EMB / 4)];
    if (i1 < 64) e1 = e4[(size_t)i1 * (EMB / 4)];

    while (i0 < 64) {
        int i2 = rem ? (__ffsll((long long)rem) - 1) : 64;
        if (i2 < 64) rem &= rem - 1;

        ulonglong2 e = e0;
        e0 = e1;
        if (i2 < 64) e1 = e4[(size_t)i2 * (EMB / 4)];

        // scores: per head 2 packed FMAs over this lane's 4 dims, then h-sum
        float v[8];
#pragma unroll
        for (int h = 0; h < 8; h++) {
            unsigned long long s2;
            MUL2(s2, p01[h], e.x);
            FMA2(s2, p23[h], e.y, s2);
            unsigned lo, hi;
            asm("mov.b64 {%0, %1}, %2;" : "=r"(lo), "=r"(hi) : "l"(s2));
            v[h] = __uint_as_float(lo) + __uint_as_float(hi);
        }

        // 9-shfl half-exchange butterfly: quad (4h..4h+3) ends with head h's dot
#pragma unroll
        for (int j = 0; j < 4; j++) {
            float o = __shfl_xor_sync(0xffffffffu, (lane & 16) ? v[j] : v[j + 4], 16);
            v[j] = ((lane & 16) ? v[j + 4] : v[j]) + o;
        }
#pragma unroll
        for (int j = 0; j < 2; j++) {
            float o = __shfl_xor_sync(0xffffffffu, (lane & 8) ? v[j] : v[j + 2], 8);
            v[j] = ((lane & 8) ? v[j + 2] : v[j]) + o;
        }
        {
            float o = __shfl_xor_sync(0xffffffffu, (lane & 4) ? v[0] : v[1], 4);
            v[0] = ((lane & 4) ? v[1] : v[0]) + o;
        }
        v[0] += __shfl_xor_sync(0xffffffffu, v[0], 2);
        v[0] += __shfl_xor_sync(0xffffffffu, v[0], 1);

        float wexp = __expf(v[0] + qb_l);
        lacc += wexp;

#pragma unroll
        for (int h = 0; h < 8; h++) {
            float wh = __shfl_sync(0xffffffffu, wexp, h * 4);
            unsigned long long wh2;
            unsigned whu = __float_as_uint(wh);
            asm("mov.b64 %0, {%1, %1};" : "=l"(wh2) : "r"(whu));
            FMA2(acc01[h], wh2, e.x, acc01[h]);
            FMA2(acc23[h], wh2, e.y, acc23[h]);
        }
        i0 = i1; i1 = i2;
    }

    // Cross-warp reduce in SMEM, one partial write per CTA.
    __shared__ float4 sAcc[4 * 8 * 32];   // [warp][head][lane], 16 KB
    __shared__ float  sL[4][8];
#pragma unroll
    for (int h = 0; h < 8; h++) {
        unsigned a0, a1, a2, a3;
        asm("mov.b64 {%0, %1}, %2;" : "=r"(a0), "=r"(a1) : "l"(acc01[h]));
        asm("mov.b64 {%0, %1}, %2;" : "=r"(a2), "=r"(a3) : "l"(acc23[h]));
        sAcc[(w * 8 + h) * 32 + lane] = make_float4(__uint_as_float(a0), __uint_as_float(a1),
                                                    __uint_as_float(a2), __uint_as_float(a3));
    }
    if ((lane & 3) == 0) sL[w][myHead] = lacc;
    __syncthreads();

    const int t = threadIdx.x;
    float4* outA = (float4*)g_partA + ((size_t)sIdx * BATCH + b) * 256;
#pragma unroll
    for (int r = 0; r < 2; r++) {
        int idx = r * 128 + t;            // [head][lane] flat index, 0..255
        float4 a = sAcc[idx];
#pragma unroll
        for (int ww = 1; ww < 4; ww++) {
            float4 o = sAcc[ww * 256 + idx];
            a.x += o.x; a.y += o.y; a.z += o.z; a.w += o.w;
        }
        outA[idx] = a;
    }
    if (t < 8) {
        float l = 0.f;
#pragma unroll
        for (int ww = 0; ww < 4; ww++) l += sL[ww][t];
        g_partL[(sIdx * BATCH + b) * HEADS + t] = l;
    }
}

// ============================================================================
// Kernel 3: combine splits, then V projection on the tiny per-head context
// vectors: out[b,o] = (ctx_h . Wv[o,:]) * (1/l_h) + bv[o].
// Warp-cooperative coalesced Wv reads; float4 partial gather.
// ============================================================================
__global__ void k_combine(const float* __restrict__ Wv, const float* __restrict__ bv,
                          float* __restrict__ out)
{
    const int b = blockIdx.x, t = threadIdx.x;   // 128 threads
    __shared__ float ctxs[HEADS][EMB];           // unnormalized
    __shared__ float invl[HEADS];
    if (t < 8) {
        float l = 0.f;
#pragma unroll
        for (int s = 0; s < SPLITS; s++) l += g_partL[(s * BATCH + b) * HEADS + t];
        invl[t] = 1.f / l;
    }
    // gather partials as float4: 256 float4 tasks over 128 threads
#pragma unroll
    for (int r2 = 0; r2 < 2; r2++) {
        int id = r2 * 128 + t;
        int h = id >> 5, q = id & 31;
        float4 a = make_float4(0.f, 0.f, 0.f, 0.f);
#pragma unroll
        for (int s = 0; s < SPLITS; s++) {
            float4 o = ((const float4*)g_partA)[((size_t)(s * BATCH + b) * HEADS + h) * 32 + q];
            a.x += o.x; a.y += o.y; a.z += o.z; a.w += o.w;
        }
        ((float4*)ctxs[h])[q] = a;
    }
    __syncthreads();

    // out mat-vec: 8-lane groups per output row, coalesced Wv reads.
    const int w = t >> 5, lane = t & 31, g = lane >> 3, k8 = lane & 7;
#pragma unroll 4
    for (int i = 0; i < 8; i++) {
        const int r = w * 32 + i * 4 + g;
        const int h = r >> 4;
        const float4* wr = (const float4*)(Wv + r * EMB);
        const float4* c4 = (const float4*)ctxs[h];
        float part = 0.f;
#pragma unroll
        for (int j = 0; j < 4; j++) {
            float4 wv = wr[k8 + 8 * j];
            float4 c  = c4[k8 + 8 * j];
            part = fmaf(wv.x, c.x, part); part = fmaf(wv.y, c.y, part);
            part = fmaf(wv.z, c.z, part); part = fmaf(wv.w, c.w, part);
        }
        part += __shfl_xor_sync(0xffffffffu, part, 4);
        part += __shfl_xor_sync(0xffffffffu, part, 2);
        part += __shfl_xor_sync(0xffffffffu, part, 1);
        if (k8 == 0) out[b * EMB + r] = fmaf(part, invl[h], bv[r]);
    }
}

// ============================================================================
extern "C" void kernel_launch(void* const* d_in, const int* in_sizes, int n_in,
                              void* d_out, int out_size)
{
    const float* ctx = (const float*)d_in[0];
    const float* emb = (const float*)d_in[1];
    const void*  msk = d_in[2];
    const float* Wq  = (const float*)d_in[3];
    const float* bq  = (const float*)d_in[4];
    const float* Wk  = (const float*)d_in[5];
    const float* bk  = (const float*)d_in[6];
    const float* Wv  = (const float*)d_in[7];
    const float* bv  = (const float*)d_in[8];
    float* out = (float*)d_out;

    k_prep<<<BATCH, 128>>>(ctx, Wq, bq, Wk, bk, (const unsigned*)msk);
    k_attn<<<dim3(SPLITS, BATCH), 128>>>(emb, msk);
    k_combine<<<BATCH, 128>>>(Wv, bv, out);
}

// round 11
// speedup vs baseline: 1.9344x; 1.0811x over previous
#include <cuda_runtime.h>
#include <cstdint>

#define BATCH 256
#define NNODE 2048
#define EMB   128
#define HEADS 8
#define DK    16
#define SPLITS 8
#define CHUNK (NNODE / SPLITS)   // 256 rows per CTA, 64 per warp (4 warps)

// packed dual-fp32 ops (sm_103a FFMA2 path — only reachable via PTX)
#define FMA2(d, a, b, c) asm("fma.rn.f32x2 %0, %1, %2, %3;" : "=l"(d) : "l"(a), "l"(b), "l"(c))
#define MUL2(d, a, b)    asm("mul.rn.f32x2 %0, %1, %2;"     : "=l"(d) : "l"(a), "l"(b))

// ---- scratch (no allocations allowed in kernel_launch) ----
__device__ float g_P[BATCH * HEADS * EMB];                 // P[b,h,:] = scale * Wk^T q
__device__ float g_qb[BATCH * HEADS];                      // scale * q_h . bk_h
__device__ float g_partA[SPLITS * BATCH * HEADS * EMB];    // 8 MB partial weighted-emb sums
__device__ float g_partL[SPLITS * BATCH * HEADS];          // partial softmax denominators
__device__ int   g_mask_fmt;                               // 1 = 4-byte elements, 0 = 1-byte

// ============================================================================
// Kernel 1: grid (2, BATCH) — 512 CTAs so all are resident in one wave.
// Each CTA: q = ctx@Wq^T+bq (redundant across halves, tiny), then P for its
// 4 heads. Mask probe parallelized across block (0,0).
// ============================================================================
__global__ void k_prep(const float* __restrict__ ctx,
                       const float* __restrict__ Wq, const float* __restrict__ bq,
                       const float* __restrict__ Wk, const float* __restrict__ bk,
                       const unsigned* __restrict__ maskw)
{
    const int half = blockIdx.x, b = blockIdx.y, t = threadIdx.x;   // 128 threads
    __shared__ float cs[EMB], qs[EMB];
    __shared__ int sGood;

    // Parallel mask element-width probe (block (0,0) only): 4-byte bools are
    // words in {0, 1, 0x3F800000}; byte-packed bools match only ~12.5%.
    if (b == 0 && half == 0) {
        if (t == 0) sGood = 0;
        cs[t] = ctx[b * EMB + t];
        __syncthreads();
        int good = 0;
#pragma unroll
        for (int i = 0; i < 8; i++) {
            unsigned w = maskw[t * 8 + i];
            good += (w == 0u) || (w == 1u) || (w == 0x3F800000u);
        }
        atomicAdd(&sGood, good);
        __syncthreads();
        if (t == 0) g_mask_fmt = (sGood >= 922) ? 1 : 0;
    } else {
        cs[t] = ctx[b * EMB + t];
        __syncthreads();
    }

    // q[r] = bq[r] + ctx_b . Wq[r,:] — 8-lane groups per row, coalesced.
    {
        const int w = t >> 5, lane = t & 31, g = lane >> 3, k8 = lane & 7;
        const float4* cs4 = (const float4*)cs;
#pragma unroll 4
        for (int i = 0; i < 8; i++) {
            const int r = w * 32 + i * 4 + g;
            const float4* wr = (const float4*)(Wq + r * EMB);
            float part = 0.f;
#pragma unroll
            for (int j = 0; j < 4; j++) {
                float4 wv = wr[k8 + 8 * j];
                float4 c  = cs4[k8 + 8 * j];
                part = fmaf(wv.x, c.x, part); part = fmaf(wv.y, c.y, part);
                part = fmaf(wv.z, c.z, part); part = fmaf(wv.w, c.w, part);
            }
            part += __shfl_xor_sync(0xffffffffu, part, 4);
            part += __shfl_xor_sync(0xffffffffu, part, 2);
            part += __shfl_xor_sync(0xffffffffu, part, 1);
            if (k8 == 0) qs[r] = part + bq[r];
        }
    }
    __syncthreads();

    const float scale = 0.25f;   // 1/sqrt(16)
#pragma unroll
    for (int hl = 0; hl < 4; hl++) {
        const int h = half * 4 + hl;
        float p = 0.f;
#pragma unroll
        for (int d = 0; d < DK; d++)
            p = fmaf(qs[h * DK + d], Wk[(h * DK + d) * EMB + t], p);
        g_P[(b * HEADS + h) * EMB + t] = p * scale;
    }
    if (t < 4) {
        const int h = half * 4 + t;
        float s = 0.f;
#pragma unroll
        for (int d = 0; d < DK; d++) s = fmaf(qs[h * DK + d], bk[h * DK + d], s);
        g_qb[b * HEADS + h] = s * scale;
    }
}

// ============================================================================
// Kernel 2: streaming masked softmax + weighted embedding accumulation.
// Grid (SPLITS, BATCH), 128 threads (4 warps), 64 rows per warp; masked rows
// skipped exactly (exp(-1e6)==0 in f32). Rows processed in BATCHES OF 4 with
// interleaved butterflies — 4 independent shuffle chains hide SHFL latency.
// Next batch's 4 loads issue before current batch's math (prefetch).
// ============================================================================
__global__ void __launch_bounds__(128) k_attn(const float* __restrict__ emb,
                                              const void* __restrict__ maskp)
{
    const int sIdx = blockIdx.x, b = blockIdx.y;
    const int w = threadIdx.x >> 5, lane = threadIdx.x & 31;
    const int myHead = (lane >> 2) & 7;

    // Per-lane slice of P, pre-packed as f32x2 pairs: dims lane*4 .. lane*4+3
    unsigned long long p01[8], p23[8];
    {
        const ulonglong2* Pv = (const ulonglong2*)g_P + (size_t)b * (HEADS * EMB / 4);
#pragma unroll
        for (int h = 0; h < 8; h++) {
            ulonglong2 t2 = Pv[h * 32 + lane];
            p01[h] = t2.x; p23[h] = t2.y;
        }
    }
    const float qb_l = g_qb[b * HEADS + myHead];

    const int rowBase = sIdx * CHUNK + w * 64;
    const size_t mbase = (size_t)b * NNODE + rowBase;

    bool um0, um1;   // "unmasked" = keep
    if (g_mask_fmt) {
        const unsigned* mi = (const unsigned*)maskp;
        um0 = (mi[mbase + lane]      == 0u);
        um1 = (mi[mbase + 32 + lane] == 0u);
    } else {
        const unsigned char* mu = (const unsigned char*)maskp;
        um0 = (mu[mbase + lane]      == 0);
        um1 = (mu[mbase + 32 + lane] == 0);
    }
    unsigned long long rem =
        (unsigned long long)__ballot_sync(0xffffffffu, um0) |
        ((unsigned long long)__ballot_sync(0xffffffffu, um1) << 32);

    // Packed accumulators: acc01[h] = dims (4l, 4l+1), acc23[h] = (4l+2, 4l+3)
    unsigned long long acc01[8], acc23[8];
#pragma unroll
    for (int h = 0; h < 8; h++) { acc01[h] = 0ull; acc23[h] = 0ull; }
    float lacc = 0.f;

    const ulonglong2* e4 = (const ulonglong2*)emb + ((size_t)b * NNODE + rowBase) * (EMB / 4) + lane;

    int c[4], n[4];
    ulonglong2 E[4], N[4];
#pragma unroll
    for (int j = 0; j < 4; j++) {
        c[j] = rem ? (__ffsll((long long)rem) - 1) : 64;
        if (c[j] < 64) rem &= rem - 1;
    }
#pragma unroll
    for (int j = 0; j < 4; j++) {
        E[j].x = 0ull; E[j].y = 0ull;
        if (c[j] < 64) E[j] = e4[(size_t)c[j] * (EMB / 4)];
    }

    while (c[0] < 64) {
        // extract + prefetch next batch
#pragma unroll
        for (int j = 0; j < 4; j++) {
            n[j] = rem ? (__ffsll((long long)rem) - 1) : 64;
            if (n[j] < 64) rem &= rem - 1;
        }
#pragma unroll
        for (int j = 0; j < 4; j++) {
            N[j].x = 0ull; N[j].y = 0ull;
            if (n[j] < 64) N[j] = e4[(size_t)n[j] * (EMB / 4)];
        }

        // scores: per row, per head: 2 packed FMAs over this lane's 4 dims
        float v[4][8];
#pragma unroll
        for (int r = 0; r < 4; r++)
#pragma unroll
            for (int h = 0; h < 8; h++) {
                unsigned long long s2;
                MUL2(s2, p01[h], E[r].x);
                FMA2(s2, p23[h], E[r].y, s2);
                unsigned lo, hi;
                asm("mov.b64 {%0, %1}, %2;" : "=r"(lo), "=r"(hi) : "l"(s2));
                v[r][h] = __uint_as_float(lo) + __uint_as_float(hi);
            }

        // 4 interleaved 9-shfl butterflies (independent chains -> ILP)
#pragma unroll
        for (int j = 0; j < 4; j++)
#pragma unroll
            for (int r = 0; r < 4; r++) {
                float o = __shfl_xor_sync(0xffffffffu, (lane & 16) ? v[r][j] : v[r][j + 4], 16);
                v[r][j] = ((lane & 16) ? v[r][j + 4] : v[r][j]) + o;
            }
#pragma unroll
        for (int j = 0; j < 2; j++)
#pragma unroll
            for (int r = 0; r < 4; r++) {
                float o = __shfl_xor_sync(0xffffffffu, (lane & 8) ? v[r][j] : v[r][j + 2], 8);
                v[r][j] = ((lane & 8) ? v[r][j + 2] : v[r][j]) + o;
            }
#pragma unroll
        for (int r = 0; r < 4; r++) {
            float o = __shfl_xor_sync(0xffffffffu, (lane & 4) ? v[r][0] : v[r][1], 4);
            v[r][0] = ((lane & 4) ? v[r][1] : v[r][0]) + o;
        }
#pragma unroll
        for (int r = 0; r < 4; r++) v[r][0] += __shfl_xor_sync(0xffffffffu, v[r][0], 2);
#pragma unroll
        for (int r = 0; r < 4; r++) v[r][0] += __shfl_xor_sync(0xffffffffu, v[r][0], 1);

        float wexp[4];
#pragma unroll
        for (int r = 0; r < 4; r++)
            wexp[r] = (c[r] < 64) ? __expf(v[r][0] + qb_l) : 0.f;
        lacc += (wexp[0] + wexp[1]) + (wexp[2] + wexp[3]);

#pragma unroll
        for (int h = 0; h < 8; h++) {
#pragma unroll
            for (int r = 0; r < 4; r++) {
                float wh = __shfl_sync(0xffffffffu, wexp[r], h * 4);
                unsigned long long wh2;
                unsigned whu = __float_as_uint(wh);
                asm("mov.b64 %0, {%1, %1};" : "=l"(wh2) : "r"(whu));
                FMA2(acc01[h], wh2, E[r].x, acc01[h]);
                FMA2(acc23[h], wh2, E[r].y, acc23[h]);
            }
        }
#pragma unroll
        for (int j = 0; j < 4; j++) { c[j] = n[j]; E[j] = N[j]; }
    }

    // Cross-warp reduce in SMEM, one partial write per CTA.
    __shared__ float4 sAcc[4 * 8 * 32];   // [warp][head][lane], 16 KB
    __shared__ float  sL[4][8];
#pragma unroll
    for (int h = 0; h < 8; h++) {
        unsigned a0, a1, a2, a3;
        asm("mov.b64 {%0, %1}, %2;" : "=r"(a0), "=r"(a1) : "l"(acc01[h]));
        asm("mov.b64 {%0, %1}, %2;" : "=r"(a2), "=r"(a3) : "l"(acc23[h]));
        sAcc[(w * 8 + h) * 32 + lane] = make_float4(__uint_as_float(a0), __uint_as_float(a1),
                                                    __uint_as_float(a2), __uint_as_float(a3));
    }
    if ((lane & 3) == 0) sL[w][myHead] = lacc;
    __syncthreads();

    const int t = threadIdx.x;
    float4* outA = (float4*)g_partA + ((size_t)sIdx * BATCH + b) * 256;
#pragma unroll
    for (int r = 0; r < 2; r++) {
        int idx = r * 128 + t;            // [head][lane] flat index, 0..255
        float4 a = sAcc[idx];
#pragma unroll
        for (int ww = 1; ww < 4; ww++) {
            float4 o = sAcc[ww * 256 + idx];
            a.x += o.x; a.y += o.y; a.z += o.z; a.w += o.w;
        }
        outA[idx] = a;
    }
    if (t < 8) {
        float l = 0.f;
#pragma unroll
        for (int ww = 0; ww < 4; ww++) l += sL[ww][t];
        g_partL[(sIdx * BATCH + b) * HEADS + t] = l;
    }
}

// ============================================================================
// Kernel 3: grid (2, BATCH) — combine splits, then V projection:
// out[b,o] = (ctx_h . Wv[o,:]) * (1/l_h) + bv[o]. Each half-CTA handles 64
// outputs (4 heads). Warp-cooperative coalesced Wv reads.
// ============================================================================
__global__ void k_combine(const float* __restrict__ Wv, const float* __restrict__ bv,
                          float* __restrict__ out)
{
    const int half = blockIdx.x, b = blockIdx.y, t = threadIdx.x;   // 128 threads
    __shared__ float ctxs[4][EMB];               // unnormalized, heads half*4..+3
    __shared__ float invl[4];
    if (t < 4) {
        const int h = half * 4 + t;
        float l = 0.f;
#pragma unroll
        for (int s = 0; s < SPLITS; s++) l += g_partL[(s * BATCH + b) * HEADS + h];
        invl[t] = 1.f / l;
    }
    // gather partials as float4: 128 float4 tasks over 128 threads
    {
        int hl = t >> 5, q = t & 31;
        int h = half * 4 + hl;
        float4 a = make_float4(0.f, 0.f, 0.f, 0.f);
#pragma unroll
        for (int s = 0; s < SPLITS; s++) {
            float4 o = ((const float4*)g_partA)[((size_t)(s * BATCH + b) * HEADS + h) * 32 + q];
            a.x += o.x; a.y += o.y; a.z += o.z; a.w += o.w;
        }
        ((float4*)ctxs[hl])[q] = a;
    }
    __syncthreads();

    // out mat-vec: 8-lane groups per output row, coalesced Wv reads.
    // Rows r_local in [0,64); head_local = r_local>>4 = w (16 rows/head).
    const int w = t >> 5, lane = t & 31, g = lane >> 3, k8 = lane & 7;
#pragma unroll
    for (int i = 0; i < 4; i++) {
        const int rl = w * 16 + i * 4 + g;       // 0..63
        const int r = half * 64 + rl;            // global output row
        const float4* wr = (const float4*)(Wv + r * EMB);
        const float4* c4 = (const float4*)ctxs[w];
        float part = 0.f;
#pragma unroll
        for (int j = 0; j < 4; j++) {
            float4 wv = wr[k8 + 8 * j];
            float4 c  = c4[k8 + 8 * j];
            part = fmaf(wv.x, c.x, part); part = fmaf(wv.y, c.y, part);
            part = fmaf(wv.z, c.z, part); part = fmaf(wv.w, c.w, part);
        }
        part += __shfl_xor_sync(0xffffffffu, part, 4);
        part += __shfl_xor_sync(0xffffffffu, part, 2);
        part += __shfl_xor_sync(0xffffffffu, part, 1);
        if (k8 == 0) out[b * EMB + r] = fmaf(part, invl[w], bv[r]);
    }
}

// ============================================================================
extern "C" void kernel_launch(void* const* d_in, const int* in_sizes, int n_in,
                              void* d_out, int out_size)
{
    const float* ctx = (const float*)d_in[0];
    const float* emb = (const float*)d_in[1];
    const void*  msk = d_in[2];
    const float* Wq  = (const float*)d_in[3];
    const float* bq  = (const float*)d_in[4];
    const float* Wk  = (const float*)d_in[5];
    const float* bk  = (const float*)d_in[6];
    const float* Wv  = (const float*)d_in[7];
    const float* bv  = (const float*)d_in[8];
    float* out = (float*)d_out;

    k_prep<<<dim3(2, BATCH), 128>>>(ctx, Wq, bq, Wk, bk, (const unsigned*)msk);
    k_attn<<<dim3(SPLITS, BATCH), 128>>>(emb, msk);
    k_combine<<<dim3(2, BATCH), 128>>>(Wv, bv, out);
}

// round 13
// speedup vs baseline: 1.9488x; 1.0074x over previous
#include <cuda_runtime.h>
#include <cstdint>

#define BATCH 256
#define NNODE 2048
#define EMB   128
#define HEADS 8
#define DK    16
#define SPLITS 8
#define CHUNK (NNODE / SPLITS)   // 256 rows per CTA, 64 per warp (4 warps)
#define NB    4                  // batches per k_prep CTA

// packed dual-fp32 ops (sm_103a FFMA2 path — only reachable via PTX)
#define FMA2(d, a, b, c) asm("fma.rn.f32x2 %0, %1, %2, %3;" : "=l"(d) : "l"(a), "l"(b), "l"(c))
#define MUL2(d, a, b)    asm("mul.rn.f32x2 %0, %1, %2;"     : "=l"(d) : "l"(a), "l"(b))
#define EX2(d, a)        asm("ex2.approx.f32 %0, %1;" : "=f"(d) : "f"(a))

// ---- scratch (no allocations allowed in kernel_launch) ----
__device__ float g_P[BATCH * HEADS * EMB];                 // P[b,h,:] = scale*log2e * Wk^T q
__device__ float g_qb[BATCH * HEADS];                      // scale*log2e * q_h . bk_h
__device__ float g_partA[SPLITS * BATCH * HEADS * EMB];    // 8 MB partial weighted-emb sums
__device__ float g_partL[SPLITS * BATCH * HEADS];          // partial softmax denominators
__device__ int   g_mask_fmt;                               // 1 = 4-byte elements, 0 = 1-byte

// ============================================================================
// Kernel 1: grid 64 CTAs, 4 batches each. Wq staged through smem in
// transposed 32x129 tiles (coalesced LDG, conflict-free STS/LDS); every
// weight element reused 4x from registers. Then P (log2e-scaled) + qb.
// ============================================================================
__global__ void __launch_bounds__(128) k_prep(
    const float* __restrict__ ctx,
    const float* __restrict__ Wq, const float* __restrict__ bq,
    const float* __restrict__ Wk, const float* __restrict__ bk,
    const unsigned* __restrict__ maskw)
{
    const int b0 = blockIdx.x * NB, t = threadIdx.x;   // 128 threads
    __shared__ float cs[NB][EMB], qs[NB][EMB];
    __shared__ float wq_s[32][EMB + 1];                // transposed tile, padded
    __shared__ int sGood;

    // Parallel mask element-width probe (block 0 only): 4-byte bools are
    // words in {0, 1, 0x3F800000}; byte-packed bools match only ~12.5%.
    if (blockIdx.x == 0) {
        if (t == 0) sGood = 0;
        __syncthreads();
        int good = 0;
#pragma unroll
        for (int i = 0; i < 8; i++) {
            unsigned w = maskw[t * 8 + i];
            good += (w == 0u) || (w == 1u) || (w == 0x3F800000u);
        }
        atomicAdd(&sGood, good);
        __syncthreads();
        if (t == 0) g_mask_fmt = (sGood >= 922) ? 1 : 0;
    }

#pragma unroll
    for (int nb = 0; nb < NB; nb++) cs[nb][t] = ctx[(b0 + nb) * EMB + t];
    __syncthreads();

    // q[nb][t] = bq[t] + cs[nb] . Wq[t,:]  via 4 k-tiles of 32
    float qa[NB] = {0.f, 0.f, 0.f, 0.f};
    const int kl = t & 31, wp = t >> 5;
#pragma unroll
    for (int kt = 0; kt < 4; kt++) {
        // stage Wq[:, kt*32 .. +32) transposed: warp reads a row per iter
#pragma unroll 8
        for (int i = 0; i < 32; i++) {
            int r = i * 4 + wp;
            wq_s[kl][r] = Wq[r * EMB + kt * 32 + kl];
        }
        __syncthreads();
#pragma unroll 8
        for (int kk = 0; kk < 32; kk++) {
            float wv = wq_s[kk][t];
            float c0 = cs[0][kt * 32 + kk], c1 = cs[1][kt * 32 + kk];
            float c2 = cs[2][kt * 32 + kk], c3 = cs[3][kt * 32 + kk];
            qa[0] = fmaf(c0, wv, qa[0]); qa[1] = fmaf(c1, wv, qa[1]);
            qa[2] = fmaf(c2, wv, qa[2]); qa[3] = fmaf(c3, wv, qa[3]);
        }
        __syncthreads();
    }
    {
        float bqt = bq[t];
#pragma unroll
        for (int nb = 0; nb < NB; nb++) qs[nb][t] = qa[nb] + bqt;
    }
    __syncthreads();

    // scale = (1/sqrt(dk)) * log2(e) so attn uses raw EX2
    const float scale = 0.25f * 1.4426950408889634f;
#pragma unroll
    for (int h = 0; h < HEADS; h++) {
        float p[NB] = {0.f, 0.f, 0.f, 0.f};
#pragma unroll
        for (int d = 0; d < DK; d++) {
            float wk = Wk[(h * DK + d) * EMB + t];
#pragma unroll
            for (int nb = 0; nb < NB; nb++)
                p[nb] = fmaf(qs[nb][h * DK + d], wk, p[nb]);
        }
#pragma unroll
        for (int nb = 0; nb < NB; nb++)
            g_P[((b0 + nb) * HEADS + h) * EMB + t] = p[nb] * scale;
    }
    if (t < 32) {
        const int nb = t >> 3, h = t & 7;
        float s = 0.f;
#pragma unroll
        for (int d = 0; d < DK; d++) s = fmaf(qs[nb][h * DK + d], bk[h * DK + d], s);
        g_qb[(b0 + nb) * HEADS + h] = s * scale;
    }
}

// ============================================================================
// Kernel 2: streaming masked softmax + weighted embedding accumulation.
// Grid (SPLITS, BATCH), 128 threads (4 warps), 64 rows/warp; masked rows
// skipped exactly. Rows in batches of 4. Reduction = 5-stage 32-value
// half-exchange transpose-butterfly (31 shfl / 4 rows): lane l ends with the
// complete score sum for (head=l>>2, row=l&3); ONE EX2 per lane per batch;
// 32 broadcast shfls feed the packed-f32x2 accumulators.
// ============================================================================
__global__ void __launch_bounds__(128) k_attn(const float* __restrict__ emb,
                                              const void* __restrict__ maskp)
{
    const int sIdx = blockIdx.x, b = blockIdx.y;
    const int w = threadIdx.x >> 5, lane = threadIdx.x & 31;

    // Per-lane slice of P, pre-packed as f32x2 pairs: dims lane*4 .. lane*4+3
    unsigned long long p01[8], p23[8];
    {
        const ulonglong2* Pv = (const ulonglong2*)g_P + (size_t)b * (HEADS * EMB / 4);
#pragma unroll
        for (int h = 0; h < 8; h++) {
            ulonglong2 t2 = Pv[h * 32 + lane];
            p01[h] = t2.x; p23[h] = t2.y;
        }
    }
    const float qb_mine = g_qb[b * HEADS + (lane >> 2)];   // my head's bias term

    const int rowBase = sIdx * CHUNK + w * 64;
    const size_t mbase = (size_t)b * NNODE + rowBase;

    bool um0, um1;   // "unmasked" = keep
    if (g_mask_fmt) {
        const unsigned* mi = (const unsigned*)maskp;
        um0 = (mi[mbase + lane]      == 0u);
        um1 = (mi[mbase + 32 + lane] == 0u);
    } else {
        const unsigned char* mu = (const unsigned char*)maskp;
        um0 = (mu[mbase + lane]      == 0);
        um1 = (mu[mbase + 32 + lane] == 0);
    }
    unsigned long long rem =
        (unsigned long long)__ballot_sync(0xffffffffu, um0) |
        ((unsigned long long)__ballot_sync(0xffffffffu, um1) << 32);

    // Packed accumulators: acc01[h] = dims (4l, 4l+1), acc23[h] = (4l+2, 4l+3)
    unsigned long long acc01[8], acc23[8];
#pragma unroll
    for (int h = 0; h < 8; h++) { acc01[h] = 0ull; acc23[h] = 0ull; }
    float lacc = 0.f;    // my (head, row-class) partial denominator

    const ulonglong2* e4 = (const ulonglong2*)emb + ((size_t)b * NNODE + rowBase) * (EMB / 4) + lane;

    int c[4], n[4];
    ulonglong2 E[4], N[4];
#pragma unroll
    for (int j = 0; j < 4; j++) {
        c[j] = rem ? (__ffsll((long long)rem) - 1) : 64;
        if (c[j] < 64) rem &= rem - 1;
    }
#pragma unroll
    for (int j = 0; j < 4; j++) {
        E[j].x = 0ull; E[j].y = 0ull;
        if (c[j] < 64) E[j] = e4[(size_t)c[j] * (EMB / 4)];
    }

    while (c[0] < 64) {
        // extract + prefetch next batch
#pragma unroll
        for (int j = 0; j < 4; j++) {
            n[j] = rem ? (__ffsll((long long)rem) - 1) : 64;
            if (n[j] < 64) rem &= rem - 1;
        }
#pragma unroll
        for (int j = 0; j < 4; j++) {
            N[j].x = 0ull; N[j].y = 0ull;
            if (n[j] < 64) N[j] = e4[(size_t)n[j] * (EMB / 4)];
        }

        // partial scores, laid out vm[m] with m = h*4 + r
        float vm[32];
#pragma unroll
        for (int h = 0; h < 8; h++)
#pragma unroll
            for (int r = 0; r < 4; r++) {
                unsigned long long s2;
                MUL2(s2, p01[h], E[r].x);
                FMA2(s2, p23[h], E[r].y, s2);
                unsigned lo, hi;
                asm("mov.b64 {%0, %1}, %2;" : "=r"(lo), "=r"(hi) : "l"(s2));
                vm[h * 4 + r] = __uint_as_float(lo) + __uint_as_float(hi);
            }

        // 5-stage half-exchange transpose-reduce: stage with half-size V
        // binds value-bit V to lane-bit V; lane l ends with full sum of vm[l].
#pragma unroll
        for (int V = 16; V >= 1; V >>= 1) {
            const bool up = (lane & V) != 0;
#pragma unroll
            for (int j = 0; j < V; j++) {
                float lo = vm[j], hi = vm[j + V];
                float mine  = up ? hi : lo;
                float other = up ? lo : hi;
                vm[j] = mine + __shfl_xor_sync(0xffffffffu, other, V);
            }
        }

        // my row's liveness gate (row = lane&3)
        int cr = (lane & 1) ? ((lane & 2) ? c[3] : c[1])
                            : ((lane & 2) ? c[2] : c[0]);
        float wlane;
        EX2(wlane, vm[0] + qb_mine);
        wlane = (cr < 64) ? wlane : 0.f;
        lacc += wlane;

        // broadcast weights (src lane = h*4+r) + packed accumulation
#pragma unroll
        for (int h = 0; h < 8; h++) {
#pragma unroll
            for (int r = 0; r < 4; r++) {
                float wgt = __shfl_sync(0xffffffffu, wlane, h * 4 + r);
                unsigned long long wh2;
                unsigned whu = __float_as_uint(wgt);
                asm("mov.b64 %0, {%1, %1};" : "=l"(wh2) : "r"(whu));
                FMA2(acc01[h], wh2, E[r].x, acc01[h]);
                FMA2(acc23[h], wh2, E[r].y, acc23[h]);
            }
        }
#pragma unroll
        for (int j = 0; j < 4; j++) { c[j] = n[j]; E[j] = N[j]; }
    }

    // quad-sum the denominator partials (4 row-classes per head)
    lacc += __shfl_xor_sync(0xffffffffu, lacc, 1);
    lacc += __shfl_xor_sync(0xffffffffu, lacc, 2);

    // Cross-warp reduce in SMEM, one partial write per CTA.
    __shared__ float4 sAcc[4 * 8 * 32];   // [warp][head][lane], 16 KB
    __shared__ float  sL[4][8];
#pragma unroll
    for (int h = 0; h < 8; h++) {
        unsigned a0, a1, a2, a3;
        asm("mov.b64 {%0, %1}, %2;" : "=r"(a0), "=r"(a1) : "l"(acc01[h]));
        asm("mov.b64 {%0, %1}, %2;" : "=r"(a2), "=r"(a3) : "l"(acc23[h]));
        sAcc[(w * 8 + h) * 32 + lane] = make_float4(__uint_as_float(a0), __uint_as_float(a1),
                                                    __uint_as_float(a2), __uint_as_float(a3));
    }
    if ((lane & 3) == 0) sL[w][lane >> 2] = lacc;
    __syncthreads();

    const int t = threadIdx.x;
    float4* outA = (float4*)g_partA + ((size_t)sIdx * BATCH + b) * 256;
#pragma unroll
    for (int r = 0; r < 2; r++) {
        int idx = r * 128 + t;            // [head][lane] flat index, 0..255
        float4 a = sAcc[idx];
#pragma unroll
        for (int ww = 1; ww < 4; ww++) {
            float4 o = sAcc[ww * 256 + idx];
            a.x += o.x; a.y += o.y; a.z += o.z; a.w += o.w;
        }
        outA[idx] = a;
    }
    if (t < 8) {
        float l = 0.f;
#pragma unroll
        for (int ww = 0; ww < 4; ww++) l += sL[ww][t];
        g_partL[(sIdx * BATCH + b) * HEADS + t] = l;
    }
}

// ============================================================================
// Kernel 3: grid (2, BATCH) — combine splits, then V projection:
// out[b,o] = (ctx_h . Wv[o,:]) * (1/l_h) + bv[o].
// ============================================================================
__global__ void k_combine(const float* __restrict__ Wv, const float* __restrict__ bv,
                          float* __restrict__ out)
{
    const int half = blockIdx.x, b = blockIdx.y, t = threadIdx.x;   // 128 threads
    __shared__ float ctxs[4][EMB];               // unnormalized, heads half*4..+3
    __shared__ float invl[4];
    if (t < 4) {
        const int h = half * 4 + t;
        float l = 0.f;
#pragma unroll
        for (int s = 0; s < SPLITS; s++) l += g_partL[(s * BATCH + b) * HEADS + h];
        invl[t] = 1.f / l;
    }
    // gather partials as float4: 128 float4 tasks over 128 threads
    {
        int hl = t >> 5, q = t & 31;
        int h = half * 4 + hl;
        float4 a = make_float4(0.f, 0.f, 0.f, 0.f);
#pragma unroll
        for (int s = 0; s < SPLITS; s++) {
            float4 o = ((const float4*)g_partA)[((size_t)(s * BATCH + b) * HEADS + h) * 32 + q];
            a.x += o.x; a.y += o.y; a.z += o.z; a.w += o.w;
        }
        ((float4*)ctxs[hl])[q] = a;
    }
    __syncthreads();

    // out mat-vec: 8-lane groups per output row, coalesced Wv reads.
    const int w = t >> 5, lane = t & 31, g = lane >> 3, k8 = lane & 7;
#pragma unroll
    for (int i = 0; i < 4; i++) {
        const int rl = w * 16 + i * 4 + g;       // 0..63
        const int r = half * 64 + rl;            // global output row
        const float4* wr = (const float4*)(Wv + r * EMB);
        const float4* c4 = (const float4*)ctxs[w];
        float part = 0.f;
#pragma unroll
        for (int j = 0; j < 4; j++) {
            float4 wv = wr[k8 + 8 * j];
            float4 c  = c4[k8 + 8 * j];
            part = fmaf(wv.x, c.x, part); part = fmaf(wv.y, c.y, part);
            part = fmaf(wv.z, c.z, part); part = fmaf(wv.w, c.w, part);
        }
        part += __shfl_xor_sync(0xffffffffu, part, 4);
        part += __shfl_xor_sync(0xffffffffu, part, 2);
        part += __shfl_xor_sync(0xffffffffu, part, 1);
        if (k8 == 0) out[b * EMB + r] = fmaf(part, invl[w], bv[r]);
    }
}

// ============================================================================
extern "C" void kernel_launch(void* const* d_in, const int* in_sizes, int n_in,
                              void* d_out, int out_size)
{
    const float* ctx = (const float*)d_in[0];
    const float* emb = (const float*)d_in[1];
    const void*  msk = d_in[2];
    const float* Wq  = (const float*)d_in[3];
    const float* bq  = (const float*)d_in[4];
    const float* Wk  = (const float*)d_in[5];
    const float* bk  = (const float*)d_in[6];
    const float* Wv  = (const float*)d_in[7];
    const float* bv  = (const float*)d_in[8];
    float* out = (float*)d_out;

    k_prep<<<BATCH / NB, 128>>>(ctx, Wq, bq, Wk, bk, (const unsigned*)msk);
    k_attn<<<dim3(SPLITS, BATCH), 128>>>(emb, msk);
    k_combine<<<dim3(2, BATCH), 128>>>(Wv, bv, out);
}